// round 17
// baseline (speedup 1.0000x reference)
#include <cuda_runtime.h>
#include <cstdint>
#include <cstddef>

#define BB 32
#define SS 64
#define TT 64
#define HH 1024
#define VV 32000
#define G3H 3072
#define NBLK 128
#define KC 128
#define STAGE_B 36864u            // bytes per pipeline stage: 2 * 128*36*4

// ---------------- scratch (device globals; no allocation allowed) ----------------
__device__ float g_Uk[BB * SS * HH];
__device__ float g_X[TT * BB * HH];
__device__ float g_GiX[TT * BB * G3H];
__device__ float g_Hall[TT * BB * HH];
__device__ float g_Q[BB * HH];
__device__ float g_GH[BB * G3H];
__device__ float g_GI[BB * G3H];
__device__ float g_Ctx[BB * HH];
__device__ float g_Sc[BB * SS];
__device__ unsigned g_arrive;
// tf32-preconverted operands for gemmTC
__device__ unsigned g_encT[BB * SS * HH];
__device__ unsigned g_UaT[HH * HH];
__device__ unsigned g_XT[TT * BB * HH];
__device__ unsigned g_WihT[G3H * 2 * HH];
__device__ unsigned g_outwT[(size_t)VV * HH];
__device__ unsigned g_HallT[TT * BB * HH];

// ---------------- helpers ----------------
__device__ __forceinline__ float tanh_ap(float x) {
    float y; asm("tanh.approx.f32 %0, %1;" : "=f"(y) : "f"(x)); return y;
}
__device__ __forceinline__ unsigned ld_acq(unsigned* p) {
    unsigned v;
    asm volatile("ld.acquire.gpu.global.u32 %0, [%1];" : "=r"(v) : "l"(p) : "memory");
    return v;
}
__device__ __forceinline__ void red_rel_add(unsigned* p, unsigned v) {
    asm volatile("red.release.gpu.global.add.u32 [%0], %1;" :: "l"(p), "r"(v) : "memory");
}
__device__ __forceinline__ void gridbar(unsigned target) {
    __syncthreads();
    if (threadIdx.x == 0) {
        red_rel_add(&g_arrive, 1u);
        while (ld_acq(&g_arrive) < target) { }
    }
    __syncthreads();
}
__device__ __forceinline__ unsigned t32(float x) {
    unsigned r; asm("cvt.rna.tf32.f32 %0, %1;" : "=r"(r) : "f"(x)); return r;
}
__device__ __forceinline__ void mma8(float& c0, float& c1, float& c2, float& c3,
                                     unsigned a0, unsigned a1, unsigned a2, unsigned a3,
                                     unsigned b0, unsigned b1) {
    asm volatile(
        "mma.sync.aligned.m16n8k8.row.col.f32.tf32.tf32.f32 "
        "{%0,%1,%2,%3}, {%4,%5,%6,%7}, {%8,%9}, {%0,%1,%2,%3};"
        : "+f"(c0), "+f"(c1), "+f"(c2), "+f"(c3)
        : "r"(a0), "r"(a1), "r"(a2), "r"(a3), "r"(b0), "r"(b1));
}
__device__ __forceinline__ void ldsm4(unsigned& r0, unsigned& r1, unsigned& r2,
                                      unsigned& r3, unsigned addr) {
    asm volatile("ldmatrix.sync.aligned.m8n8.x4.shared.b16 {%0,%1,%2,%3}, [%4];"
                 : "=r"(r0), "=r"(r1), "=r"(r2), "=r"(r3) : "r"(addr));
}
__device__ __forceinline__ void ldsm2(unsigned& r0, unsigned& r1, unsigned addr) {
    asm volatile("ldmatrix.sync.aligned.m8n8.x2.shared.b16 {%0,%1}, [%2];"
                 : "=r"(r0), "=r"(r1) : "r"(addr));
}
__device__ __forceinline__ unsigned smem_u32(const void* p) {
    return (unsigned)__cvta_generic_to_shared(p);
}
__device__ __forceinline__ void cpa16(unsigned d, const void* s) {
    asm volatile("cp.async.cg.shared.global [%0], [%1], 16;" :: "r"(d), "l"(s) : "memory");
}

// =================================================================================
// cvt4: fp32 -> tf32(rna) bulk conversion (same rounding as previous in-GEMM cvt)
// =================================================================================
__global__ __launch_bounds__(256)
void cvt4(const float4* __restrict__ s, uint4* __restrict__ d, int n4)
{
    int i = blockIdx.x * 256 + threadIdx.x;
    if (i < n4) {
        float4 v = s[i];
        d[i] = make_uint4(t32(v.x), t32(v.y), t32(v.z), t32(v.w));
    }
}

// =================================================================================
// gemmTC: C[M,N] = A[M,1024]*W[N,ldw]^T + bias — tf32 pre-converted operands,
// cp.async 3-stage pipeline (110.6 KB dynamic smem), LDSM fragment loads.
// block 128x128, 256 thr = 8 warps (2m x 4n), warp 64x32, K-chunk 32.
// mode 0: C row-major ld=N.  mode 1: logits remap row r=t*32+b -> C[b][t*VV + n].
// =================================================================================
__global__ __launch_bounds__(256)
void gemmTC(const unsigned* __restrict__ A, int lda,
            const unsigned* __restrict__ W, int ldw,
            const float* __restrict__ bias, float* __restrict__ C, int N, int mode)
{
    extern __shared__ unsigned dsm[];           // 3 stages x (As[128][36] + Ws[128][36])
    const int tid = threadIdx.x;
    const int m0 = blockIdx.x * 128;
    const int n0 = blockIdx.y * 128;
    const int wid = tid >> 5, lane = tid & 31;
    const int gid = lane >> 2, tig = lane & 3;
    const int wm = (wid >> 2) * 64;
    const int wn = (wid & 3) * 32;

    const unsigned sbase = smem_u32(dsm);

    // LDSM per-lane fragment addresses (stage-0 base; add stage offset later)
    const int j = lane >> 3, rsel = lane & 7;
    unsigned aAddr[4], bAddr[2];
#pragma unroll
    for (int mf = 0; mf < 4; mf++)
        aAddr[mf] = sbase + (unsigned)(wm + mf * 16 + (j & 1) * 8 + rsel) * 144u
                  + (unsigned)((j >> 1) * 4) * 4u;
#pragma unroll
    for (int nfp = 0; nfp < 2; nfp++)
        bAddr[nfp] = sbase + 18432u
                   + (unsigned)(wn + (2 * nfp + (j >> 1)) * 8 + rsel) * 144u
                   + (unsigned)((j & 1) * 4) * 4u;

    // loader: row = tid>>1 (0..127), 16-col half = (tid&1)*16; 4x cp.async 16B each
    const int lrow = tid >> 1;
    const int lcb = (tid & 1) << 4;
    const unsigned* Asrc = A + (size_t)(m0 + lrow) * lda + lcb;
    const unsigned* Wsrc = W + (size_t)(n0 + lrow) * ldw + lcb;
    const unsigned dA0 = sbase + (unsigned)lrow * 144u + (unsigned)lcb * 4u;
    const unsigned dW0 = dA0 + 18432u;

    float acc[4][4][4];
#pragma unroll
    for (int i = 0; i < 4; i++)
#pragma unroll
        for (int jj = 0; jj < 4; jj++)
#pragma unroll
            for (int e = 0; e < 4; e++) acc[i][jj][e] = 0.f;

#define ISSUE_STAGE(ck)                                                   \
    do {                                                                  \
        const unsigned so_ = ((ck) % 3) * STAGE_B;                        \
        const unsigned* sa_ = Asrc + (ck) * 32;                           \
        const unsigned* sw_ = Wsrc + (ck) * 32;                           \
        cpa16(dA0 + so_ + 0,  sa_ + 0);                                   \
        cpa16(dA0 + so_ + 16, sa_ + 4);                                   \
        cpa16(dA0 + so_ + 32, sa_ + 8);                                   \
        cpa16(dA0 + so_ + 48, sa_ + 12);                                  \
        cpa16(dW0 + so_ + 0,  sw_ + 0);                                   \
        cpa16(dW0 + so_ + 16, sw_ + 4);                                   \
        cpa16(dW0 + so_ + 32, sw_ + 8);                                   \
        cpa16(dW0 + so_ + 48, sw_ + 12);                                  \
        asm volatile("cp.async.commit_group;" ::: "memory");              \
    } while (0)

    ISSUE_STAGE(0);
    ISSUE_STAGE(1);

    for (int ck = 0; ck < 32; ck++) {
        asm volatile("cp.async.wait_group 1;" ::: "memory");
        __syncthreads();
        if (ck + 2 < 32) ISSUE_STAGE(ck + 2);
        const unsigned so = (ck % 3) * STAGE_B;
#pragma unroll
        for (int ks = 0; ks < 4; ks++) {
            const unsigned ko = so + ks * 32;
            unsigned af[4][4], bf[4][2];
#pragma unroll
            for (int mf = 0; mf < 4; mf++)
                ldsm4(af[mf][0], af[mf][1], af[mf][2], af[mf][3], aAddr[mf] + ko);
#pragma unroll
            for (int nfp = 0; nfp < 2; nfp++)
                ldsm4(bf[2 * nfp][0], bf[2 * nfp][1],
                      bf[2 * nfp + 1][0], bf[2 * nfp + 1][1], bAddr[nfp] + ko);
#pragma unroll
            for (int mf = 0; mf < 4; mf++)
#pragma unroll
                for (int nf = 0; nf < 4; nf++)
                    mma8(acc[mf][nf][0], acc[mf][nf][1], acc[mf][nf][2], acc[mf][nf][3],
                         af[mf][0], af[mf][1], af[mf][2], af[mf][3],
                         bf[nf][0], bf[nf][1]);
        }
    }
#undef ISSUE_STAGE

#pragma unroll
    for (int mf = 0; mf < 4; mf++) {
#pragma unroll
        for (int rr = 0; rr < 2; rr++) {
            int m = m0 + wm + mf * 16 + gid + rr * 8;
            float* crow;
            if (mode == 1) {
                int tt = m >> 5, b = m & 31;
                crow = C + (size_t)b * ((size_t)TT * VV) + (size_t)tt * VV;
            } else {
                crow = C + (size_t)m * N;
            }
#pragma unroll
            for (int nf = 0; nf < 4; nf++) {
                int n = n0 + wn + nf * 8 + tig * 2;
                float2 v;
                v.x = acc[mf][nf][rr * 2 + 0] + bias[n];
                v.y = acc[mf][nf][rr * 2 + 1] + bias[n + 1];
                *(float2*)(crow + n) = v;
            }
        }
    }
}

// =================================================================================
// mtile32: C[32 x 32] = A[32,1024] @ W[n0:n0+32, :]^T (+bias, +init) — LDSM loads
// (unchanged from 3844us kernel)
// =================================================================================
__device__ __forceinline__ void mtile32(
    unsigned (*As)[132], unsigned (*Ws)[132],
    const float* __restrict__ A, int lda,
    const float* __restrict__ W, int ldw, int n0,
    const float* __restrict__ bias,
    const float* __restrict__ init, int ldi,
    float* __restrict__ C, int ldc, int tid)
{
    const int wid = tid >> 5, lane = tid & 31;
    const int gid = lane >> 2, tig = lane & 3;
    const int wm = (wid >> 2) * 16;
    const int wn = (wid & 3) * 8;
    const int lr = tid >> 3;
    const int lc = (tid & 7) * 16;

    const int j = lane >> 3, rsel = lane & 7;
    const unsigned aAddr = smem_u32(&As[wm + (j & 1) * 8 + rsel][(j >> 1) * 4]);
    const int j2 = (lane & 15) >> 3;
    const unsigned bAddr = smem_u32(&Ws[wn + (lane & 7)][j2 * 4]);

    float4 ra[4], rw[4];
    const float* Arow = A + (size_t)lr * lda + lc;
    const float* Wrow = W + (size_t)(n0 + lr) * ldw + lc;
#pragma unroll
    for (int jj = 0; jj < 4; jj++) {
        ra[jj] = *(const float4*)(Arow + jj * 4);
        rw[jj] = *(const float4*)(Wrow + jj * 4);
    }
    float acc[4] = {0.f, 0.f, 0.f, 0.f};

    for (int ck = 0; ck < HH / KC; ck++) {
        __syncthreads();
#pragma unroll
        for (int jj = 0; jj < 4; jj++) {
            uint4 av = make_uint4(t32(ra[jj].x), t32(ra[jj].y), t32(ra[jj].z), t32(ra[jj].w));
            uint4 wv = make_uint4(t32(rw[jj].x), t32(rw[jj].y), t32(rw[jj].z), t32(rw[jj].w));
            *(uint4*)&As[lr][lc + jj * 4] = av;
            *(uint4*)&Ws[lr][lc + jj * 4] = wv;
        }
        __syncthreads();
        if (ck + 1 < HH / KC) {
            const int kc = (ck + 1) * KC;
#pragma unroll
            for (int jj = 0; jj < 4; jj++) {
                ra[jj] = *(const float4*)(Arow + kc + jj * 4);
                rw[jj] = *(const float4*)(Wrow + kc + jj * 4);
            }
        }
#pragma unroll
        for (int kk = 0; kk < KC; kk += 8) {
            const unsigned ko = kk * 4;
            unsigned a0, a1, a2, a3, b0, b1;
            ldsm4(a0, a1, a2, a3, aAddr + ko);
            ldsm2(b0, b1, bAddr + ko);
            mma8(acc[0], acc[1], acc[2], acc[3], a0, a1, a2, a3, b0, b1);
        }
    }
#pragma unroll
    for (int rr = 0; rr < 2; rr++) {
        const int m = wm + gid + rr * 8;
#pragma unroll
        for (int cc = 0; cc < 2; cc++) {
            const int nn = n0 + wn + tig * 2 + cc;
            float v = acc[rr * 2 + cc];
            if (bias) v += bias[nn];
            if (init) v += init[(size_t)m * ldi + nn];
            C[(size_t)m * ldc + nn] = v;
        }
    }
}

// ---------------- persistent recurrence: 5-phase structure (proven, unchanged) ---
__global__ __launch_bounds__(256, 1)
void recur(const float* __restrict__ h0, const float* __restrict__ enc,
           const float* __restrict__ Wa_w, const float* __restrict__ Wa_b,
           const float* __restrict__ W_hh, const float* __restrict__ b_hh,
           const float* __restrict__ W_ih,
           const float* __restrict__ Va_w, const float* __restrict__ Va_b,
           float* __restrict__ attn_out, float* __restrict__ hT_out)
{
    __shared__ unsigned As[32][132];
    __shared__ unsigned Ws[32][132];
    __shared__ float smq[HH];
    __shared__ float smva[HH];
    __shared__ float smsc[SS];
    __shared__ float smex[SS];

    const int blk = blockIdx.x;
    const int tid = threadIdx.x;
    unsigned bt = 0;

    for (int t = 0; t < TT; t++) {
        const float* hid = (t == 0) ? h0 : (g_Hall + (size_t)(t - 1) * BB * HH);

        // phase A: q (tasks 0..31) + GH (tasks 32..127)
        if (blk < 32)
            mtile32(As, Ws, hid, HH, Wa_w, HH, blk * 32, Wa_b,
                    nullptr, 0, g_Q, HH, tid);
        else
            mtile32(As, Ws, hid, HH, W_hh, HH, (blk - 32) * 32, b_hh,
                    nullptr, 0, g_GH, G3H, tid);
        bt += NBLK; gridbar(bt);

        // phase B1: scores[b][s] = Va . tanh(q[b] + Uk[b,s]) + Va_b
        {
            const int b = blk >> 2, sg = (blk & 3) * 16;
            for (int i = tid; i < HH; i += 256) {
                smq[i] = g_Q[b * HH + i];
                smva[i] = Va_w[i];
            }
            __syncthreads();
            const int w = tid >> 5, lane = tid & 31;
#pragma unroll
            for (int si = 0; si < 2; si++) {
                int s = sg + w * 2 + si;
                const float* uk = g_Uk + (size_t)(b * SS + s) * HH;
                float sum = 0.f;
#pragma unroll 8
                for (int h = lane; h < HH; h += 32)
                    sum += smva[h] * tanh_ap(smq[h] + uk[h]);
#pragma unroll
                for (int o = 16; o; o >>= 1)
                    sum += __shfl_xor_sync(0xffffffffu, sum, o);
                if (lane == 0) g_Sc[b * SS + s] = sum + Va_b[0];
            }
        }
        bt += NBLK; gridbar(bt);

        // phase B2: softmax + attentions output + context (h-quartered)
        {
            const int b = blk >> 2, hq = blk & 3;
            if (tid < SS) smsc[tid] = g_Sc[b * SS + tid];
            __syncthreads();
            float mx = -1e30f;
#pragma unroll
            for (int s = 0; s < SS; s++) mx = fmaxf(mx, smsc[s]);
            if (tid < SS) smex[tid] = expf(smsc[tid] - mx);
            __syncthreads();
            float sum = 0.f;
#pragma unroll
            for (int s = 0; s < SS; s++) sum += smex[s];
            const float inv = 1.f / sum;
            const int h = hq * 256 + tid;
            const float* eb = enc + (size_t)b * SS * HH + h;
            float acc = 0.f;
#pragma unroll 8
            for (int s = 0; s < SS; s++) acc += smex[s] * eb[(size_t)s * HH];
            g_Ctx[b * HH + h] = acc * inv;
            if (hq == 0 && tid < SS)
                attn_out[(size_t)b * TT * SS + (size_t)t * SS + tid] = smex[tid] * inv;
        }
        bt += NBLK; gridbar(bt);

        // phase C: GI = GiX[t] + ctx @ W_ih[:, H:]^T   (96 tile tasks)
        if (blk < 96) {
            mtile32(As, Ws, g_Ctx, HH, W_ih + HH, 2 * HH, blk * 32, nullptr,
                    g_GiX + (size_t)t * BB * G3H, G3H, g_GI, G3H, tid);
        }
        bt += NBLK; gridbar(bt);

        // phase D: GRU combine (PyTorch semantics)
        if (blk < 32) {
            const int b = blk;
            for (int h = tid; h < HH; h += 256) {
                float ir = g_GI[b * G3H + h],           hr = g_GH[b * G3H + h];
                float iz = g_GI[b * G3H + HH + h],      hz = g_GH[b * G3H + HH + h];
                float in_ = g_GI[b * G3H + 2 * HH + h], hn = g_GH[b * G3H + 2 * HH + h];
                float r = 1.f / (1.f + expf(-(ir + hr)));
                float z = 1.f / (1.f + expf(-(iz + hz)));
                float nv = tanhf(in_ + r * hn);
                float hnew = (1.f - z) * nv + z * hid[b * HH + h];
                g_Hall[(size_t)t * BB * HH + b * HH + h] = hnew;
                if (t == TT - 1) hT_out[b * HH + h] = hnew;
            }
        }
        bt += NBLK; gridbar(bt);
    }
}

// tokens: tok(b,0)=SOS=1, tok(b,t)=target[b,t-1]; gather emb rows; reset barrier
__global__ __launch_bounds__(256)
void gather_emb(const int* __restrict__ target, const float* __restrict__ emb)
{
    if (blockIdx.x == 0 && threadIdx.x == 0) g_arrive = 0;
    const int r = blockIdx.x;
    const int t = r >> 5, b = r & 31;
    const int tok = (t == 0) ? 1 : target[b * TT + (t - 1)];
    const float4* src = (const float4*)(emb + (size_t)tok * HH);
    float4* dst = (float4*)(g_X + (size_t)r * HH);
    dst[threadIdx.x] = src[threadIdx.x];
}

extern "C" void kernel_launch(void* const* d_in, const int* in_sizes, int n_in,
                              void* d_out, int out_size)
{
    (void)in_sizes; (void)n_in; (void)out_size;
    const float* enc   = (const float*)d_in[0];
    const float* h0    = (const float*)d_in[1];
    const int*   tgt   = (const int*)d_in[2];
    const float* emb   = (const float*)d_in[3];
    const float* Wa_w  = (const float*)d_in[4];
    const float* Wa_b  = (const float*)d_in[5];
    const float* Ua_w  = (const float*)d_in[6];
    const float* Ua_b  = (const float*)d_in[7];
    const float* Va_w  = (const float*)d_in[8];
    const float* Va_b  = (const float*)d_in[9];
    const float* W_ih  = (const float*)d_in[10];
    const float* W_hh  = (const float*)d_in[11];
    const float* b_ih  = (const float*)d_in[12];
    const float* b_hh  = (const float*)d_in[13];
    const float* out_w = (const float*)d_in[14];
    const float* out_b = (const float*)d_in[15];

    float* out = (float*)d_out;
    float* dec_out  = out;                                          // B*T*V
    float* hT_out   = out + (size_t)BB * TT * VV;                   // B*H
    float* attn_out = out + (size_t)BB * TT * VV + (size_t)BB * HH; // B*T*S

    float *Uk, *X, *GiX, *Hall;
    unsigned *encT, *UaT, *XT, *WihT, *outwT, *HallT;
    cudaGetSymbolAddress((void**)&Uk, g_Uk);
    cudaGetSymbolAddress((void**)&X, g_X);
    cudaGetSymbolAddress((void**)&GiX, g_GiX);
    cudaGetSymbolAddress((void**)&Hall, g_Hall);
    cudaGetSymbolAddress((void**)&encT, g_encT);
    cudaGetSymbolAddress((void**)&UaT, g_UaT);
    cudaGetSymbolAddress((void**)&XT, g_XT);
    cudaGetSymbolAddress((void**)&WihT, g_WihT);
    cudaGetSymbolAddress((void**)&outwT, g_outwT);
    cudaGetSymbolAddress((void**)&HallT, g_HallT);

    // opt-in to 110.6 KB dynamic smem for the pipelined GEMM (idempotent)
    cudaFuncSetAttribute(gemmTC, cudaFuncAttributeMaxDynamicSharedMemorySize,
                         3 * (int)STAGE_B);
    const int DSM = 3 * (int)STAGE_B;

    // Phase 0: barrier reset + token gather + tf32 conversions + invariant GEMMs
    gather_emb<<<TT * BB, 256>>>(tgt, emb);
#define CVT(srcp, dstp, nelem) \
    cvt4<<<((nelem) / 4 + 255) / 256, 256>>>((const float4*)(srcp), (uint4*)(dstp), (nelem) / 4)
    CVT(enc, encT, BB * SS * HH);
    CVT(Ua_w, UaT, HH * HH);
    CVT(X, XT, TT * BB * HH);
    CVT(W_ih, WihT, G3H * 2 * HH);
    CVT(out_w, outwT, (size_t)VV * HH);
    gemmTC<<<dim3((BB * SS) / 128, HH / 128), 256, DSM>>>(encT, HH, UaT, HH,
                                                          Ua_b, Uk, HH, 0);
    gemmTC<<<dim3((TT * BB) / 128, G3H / 128), 256, DSM>>>(XT, HH, WihT, 2 * HH,
                                                           b_ih, GiX, G3H, 0);

    // Phase 1: persistent fused recurrence (5 phases/step, tensor-core tiles)
    recur<<<NBLK, 256>>>(h0, enc, Wa_w, Wa_b, W_hh, b_hh, W_ih, Va_w, Va_b,
                         attn_out, hT_out);

    // Phase 2: batched vocab projection (tensor cores, tf32, pipelined)
    CVT(Hall, HallT, TT * BB * HH);
    gemmTC<<<dim3((TT * BB) / 128, VV / 128), 256, DSM>>>(HallT, HH, outwT, HH,
                                                          out_b, dec_out, VV, 1);
#undef CVT
}